// round 13
// baseline (speedup 1.0000x reference)
#include <cuda_runtime.h>
#include <cstdint>

#define NQ      24
#define KTOT    576
#define MSIDE   12
#define MTOT    144
#define CI      16
#define CO      16
#define HID     8
#define BATCH   32
#define DECAYF  1296.0f
#define E_F     2.7182818284590452f
#define NW      88
#define PSTRIDE 64
#define NB      296           // 2 blocks/SM on 148 SMs -> all co-resident
#define MAXC    40

// Scratch
__device__ float    g_featT2[KTOT * BATCH * CI];  // [k][c*32+b]
__device__ float    g_Wt[NW * 256];               // [w][pair]
__device__ float4   g_pts[MTOT * PSTRIDE];        // (x0, x1, bump*w, k-as-int)
__device__ int      g_cnt[MTOT];
__device__ unsigned g_bar = 0;                    // monotonic grid barrier

__device__ __forceinline__ void cp8(uint32_t dst_smem, const void* src) {
    asm volatile("cp.async.ca.shared.global [%0], [%1], 8;\n"
                 :: "r"(dst_smem), "l"(src) : "memory");
}
#define CP_COMMIT() asm volatile("cp.async.commit_group;\n" ::: "memory")
#define CP_WAIT3()  asm volatile("cp.async.wait_group 3;\n" ::: "memory")

// ---------------------------------------------------------------------------
// Fused kernel: phase A (light, balanced prep) -> grid barrier -> phase B
// (the proven R8 scalar main loop).
// ---------------------------------------------------------------------------
__global__ void __launch_bounds__(256, 2)
qc_fused(const float* __restrict__ feats,
         const float* __restrict__ W1,
         const float* __restrict__ W2,
         const float* __restrict__ W3,
         const float* __restrict__ locs,
         const float* __restrict__ qn,
         const float* __restrict__ qw,
         float* __restrict__ out)
{
    const int bid  = blockIdx.x;
    const int t    = threadIdx.x;
    const int lane = t & 31;
    const int o    = t >> 4;
    const int bh   = t & 15;

    __shared__ __align__(16) float  s_f[4][BATCH * CI];   // phase B: panels
    __shared__ __align__(16) float4 s_pts[MAXC];
    __shared__ float s_tile[32][33];                       // phase A: transpose
    __shared__ int   s_pm[MAXC];
    __shared__ int   s_off[MTOT + 1];

    // ======================= Phase A: distributed prep =======================
    // A1: transpose, one (c, 32-wide k-tile) unit per block (288 units).
    //     Coalesced on both sides: read fast along k, write fast along b.
    if (bid < 288) {
        const int c  = bid & 15;
        const int k0 = (bid >> 4) * 32;
        {
            const int kk = t & 31, b0 = t >> 5;
            #pragma unroll
            for (int b = b0; b < 32; b += 8)
                s_tile[b][kk] = feats[(b * CI + c) * KTOT + k0 + kk];
        }
        __syncthreads();
        {
            const int b = t & 31, kk0 = t >> 5;
            #pragma unroll
            for (int kk = kk0; kk < 32; kk += 8)
                g_featT2[(k0 + kk) * 512 + c * 32 + b] = s_tile[b][kk];
        }
    }
    // A2: active-point scan — warp 0 of blocks 144..287 handles m = bid-144.
    if (bid >= 144 && bid < 288 && t < 32) {
        const int m = bid - 144;
        const float lx = locs[m * 2 + 0];
        const float ly = locs[m * 2 + 1];
        int cnt = 0;
        for (int base = 0; base < KTOT; base += 32) {     // 576 = 18*32
            int k = base + t;
            int i = k / NQ, j = k - i * NQ;
            float x0 = lx - qn[j];
            float x1 = ly - qn[i];
            float r2 = x0 * x0 + x1 * x1;
            float da = DECAYF * r2 * r2;
            bool act = (da < 1.0f);
            unsigned bal = __ballot_sync(0xffffffffu, act);
            if (act) {
                int pos = cnt + __popc(bal & ((1u << t) - 1u));
                float bw = E_F * __expf(-1.0f / (1.0f - da)) * (qw[i] * qw[j]);
                g_pts[m * PSTRIDE + pos] = make_float4(x0, x1, bw, __int_as_float(k));
            }
            cnt += __popc(bal);
        }
        if (t == 0) g_cnt[m] = cnt;
    }
    // A3: weight pack — blocks 288..295 (8 blocks x 11 iters of 256).
    if (bid >= 288) {
        const int sub = bid - 288;
        #pragma unroll
        for (int j = 0; j < 11; j++) {
            int idx = (sub * 11 + j) * 256 + t;          // < 22528 = 88*256
            int w = idx >> 8, pair = idx & 255;
            float v;
            if (w < 16)      v = W1[pair * 16 + w];
            else if (w < 80) { int r = w - 16, g = r >> 3, h = r & 7;
                               v = W2[pair * 64 + h * 8 + g]; }
            else             v = W3[pair * 8 + (w - 80)];
            g_Wt[idx] = v;
        }
    }
    // A4: zero the output — one float4 per thread grid-wide (18432 needed).
    {
        int gidx = bid * 256 + t;
        if (gidx < (BATCH * CO * MTOT) / 4)
            ((float4*)out)[gidx] = make_float4(0.f, 0.f, 0.f, 0.f);
    }

    // ==================== Grid barrier (replay-safe) ====================
    __threadfence();
    __syncthreads();
    if (t == 0) {
        unsigned tk = atomicAdd(&g_bar, 1u);
        unsigned target = tk - (tk % NB) + NB;
        while (*(volatile unsigned*)&g_bar < target) { }
    }
    __syncthreads();
    __threadfence();

    // ======================= Phase B: R8 main loop =======================
    // Coalesced per-thread weight loads (lane == pair); L2-hot from phase A.
    float w1a[HID], w1b[HID], w2t[HID][HID], w3[HID];
    {
        const float* W = g_Wt + t;
        #pragma unroll
        for (int h = 0; h < HID; h++) { w1a[h] = W[h * 256]; w1b[h] = W[(8 + h) * 256]; }
        #pragma unroll
        for (int g = 0; g < HID; g++)
            #pragma unroll
            for (int h = 0; h < HID; h++) w2t[g][h] = W[(16 + g * 8 + h) * 256];
        #pragma unroll
        for (int g = 0; g < HID; g++) w3[g] = W[(80 + g) * 256];
    }

    // Warp 0: exclusive prefix over the 144 active counts
    if (t < 32) {
        int base = t * 5;
        int c0 = (base + 0 < MTOT) ? g_cnt[base + 0] : 0;
        int c1 = (base + 1 < MTOT) ? g_cnt[base + 1] : 0;
        int c2 = (base + 2 < MTOT) ? g_cnt[base + 2] : 0;
        int c3 = (base + 3 < MTOT) ? g_cnt[base + 3] : 0;
        int c4 = (base + 4 < MTOT) ? g_cnt[base + 4] : 0;
        int l0 = c0, l1 = l0 + c1, l2 = l1 + c2, l3 = l2 + c3, l4 = l3 + c4;
        int x = l4;
        #pragma unroll
        for (int d = 1; d < 32; d <<= 1) {
            int y = __shfl_up_sync(0xffffffffu, x, d);
            if (lane >= d) x += y;
        }
        int excl = x - l4;
        if (base + 0 <= MTOT) s_off[base + 0] = excl;
        if (base + 1 <= MTOT) s_off[base + 1] = excl + l0;
        if (base + 2 <= MTOT) s_off[base + 2] = excl + l1;
        if (base + 3 <= MTOT) s_off[base + 3] = excl + l2;
        if (base + 4 <= MTOT) s_off[base + 4] = excl + l3;
    }
    __syncthreads();

    const int T = s_off[MTOT];
    const int chunk = (T + NB - 1) / NB;
    const int p0 = bid * chunk;
    const int n  = min(p0 + chunk, T) - p0;
    if (n <= 0) return;

    // Preload this block's point metadata (one thread per point)
    if (t < n) {
        int p = p0 + t;
        int lo = 0, hi = MTOT;
        while (hi - lo > 1) { int mid = (lo + hi) >> 1; (s_off[mid] <= p) ? (lo = mid) : (hi = mid); }
        s_pm[t]  = lo;
        s_pts[t] = g_pts[lo * PSTRIDE + (p - s_off[lo])];
    }
    __syncthreads();

    const uint32_t sfb   = (uint32_t)__cvta_generic_to_shared(&s_f[0][0]);
    const uint32_t myoff = (uint32_t)(t * 8);

    // Prefetch points 0..2 (one commit group per point; empty groups kept)
    #pragma unroll
    for (int j = 0; j < 3; j++) {
        if (j < n)
            cp8(sfb + (uint32_t)j * 2048 + myoff,
                g_featT2 + (size_t)__float_as_int(s_pts[j].w) * 512 + t * 2);
        CP_COMMIT();
    }

    int cm = s_pm[0];
    float a0 = 0.f, a1 = 0.f;

    for (int i = 0; i < n; i++) {
        if (i + 3 < n)
            cp8(sfb + (uint32_t)((i + 3) & 3) * 2048 + myoff,
                g_featT2 + (size_t)__float_as_int(s_pts[i + 3].w) * 512 + t * 2);
        CP_COMMIT();

        const float4 pt = s_pts[i];
        const int    m  = s_pm[i];
        if (m != cm) {   // flush partials on m transition (rare)
            atomicAdd(&out[(2 * bh)     * (CO * MTOT) + o * MTOT + cm], a0);
            atomicAdd(&out[(2 * bh + 1) * (CO * MTOT) + o * MTOT + cm], a1);
            a0 = 0.f; a1 = 0.f; cm = m;
        }
        const float x0 = pt.x, x1 = pt.y, bw = pt.z;

        // Tiny MLP: 2 -> 8 (sin) -> 8 (sin) -> 1; sins on MUFU pipe
        float h1[HID];
        #pragma unroll
        for (int h = 0; h < HID; h++)
            h1[h] = __sinf(fmaf(x0, w1a[h], x1 * w1b[h]));
        float val = 0.0f;
        #pragma unroll
        for (int g = 0; g < HID; g++) {
            float acc = 0.0f;
            #pragma unroll
            for (int h = 0; h < HID; h++) acc = fmaf(h1[h], w2t[g][h], acc);
            val = fmaf(__sinf(acc), w3[g], val);
        }
        const float v = val * bw;

        CP_WAIT3();           // group i complete (<=3 newer pending)
        __syncthreads();      // panel i visible block-wide

        // Contraction: v[o,cc] via intra-warp shuffle, features from smem
        const float* fb = &s_f[i & 3][2 * bh];
        #pragma unroll
        for (int cc = 0; cc < CI; cc++) {
            float vv = __shfl_sync(0xffffffffu, v, (lane & 16) + cc);
            float2 f = *(const float2*)(fb + cc * 32);
            a0 = fmaf(vv, f.x, a0);
            a1 = fmaf(vv, f.y, a1);
        }
        __syncthreads();      // reads done before next iteration's clobber
    }

    atomicAdd(&out[(2 * bh)     * (CO * MTOT) + o * MTOT + cm], a0);
    atomicAdd(&out[(2 * bh + 1) * (CO * MTOT) + o * MTOT + cm], a1);
}

// ---------------------------------------------------------------------------
extern "C" void kernel_launch(void* const* d_in, const int* in_sizes, int n_in,
                              void* d_out, int out_size) {
    const float* feats = (const float*)d_in[0];  // (32, 16, 576)
    const float* locs  = (const float*)d_in[1];  // (144, 2)
    const float* qn    = (const float*)d_in[2];  // (24,)
    const float* qw    = (const float*)d_in[3];  // (24,)
    const float* W1    = (const float*)d_in[4];  // (16,16,2,8)
    const float* W2    = (const float*)d_in[5];  // (16,16,8,8)
    const float* W3    = (const float*)d_in[6];  // (16,16,8,1)
    float* out = (float*)d_out;                  // (32, 16, 144)

    qc_fused<<<NB, 256>>>(feats, W1, W2, W3, locs, qn, qw, out);
}

// round 14
// speedup vs baseline: 1.1047x; 1.1047x over previous
#include <cuda_runtime.h>
#include <cstdint>

#define NQ      24
#define KTOT    576
#define MSIDE   12
#define MTOT    144
#define CI      16
#define CO      16
#define HID     8
#define BATCH   32
#define DECAYF  1296.0f
#define E_F     2.7182818284590452f
#define NW      88
#define PSTRIDE 64
#define NB      296           // 2 blocks/SM on 148 SMs
#define MAXC    40

// prep block ranges (R8 layout — best measured total)
#define PB_TR   288                  // transpose: 16 c * 18 k-tiles
#define PB_SCAN (PB_TR + MTOT)       // 288..432
#define PB_W    (PB_SCAN + NW)       // 432..520
#define PB_Z    (PB_W + 72)          // 520..592

// Scratch
__device__ float  g_featT2[KTOT * BATCH * CI];  // [k][c*32+b]
__device__ float  g_Wt[NW * 256];               // [w][pair]
__device__ float4 g_pts[MTOT * PSTRIDE];        // (x0, x1, bump*w, k-as-int)
__device__ int    g_cnt[MTOT];

// ---------------------------------------------------------------------------
// Prep (R8 version verbatim): transpose + scan + weight pack + out zero.
// ---------------------------------------------------------------------------
__global__ void qc_prep(const float* __restrict__ feats,
                        const float* __restrict__ W1,
                        const float* __restrict__ W2,
                        const float* __restrict__ W3,
                        const float* __restrict__ locs,
                        const float* __restrict__ qn,
                        const float* __restrict__ qw,
                        float* __restrict__ out) {
    const int bid = blockIdx.x;
    const int t = threadIdx.x;
    if (bid < PB_TR) {
        __shared__ float tile[32][33];
        const int c  = bid & 15;
        const int k0 = (bid >> 4) * 32;
        {
            const int kk = t & 31, b0 = t >> 5;
            #pragma unroll
            for (int b = b0; b < 32; b += 8)
                tile[b][kk] = feats[(b * CI + c) * KTOT + k0 + kk];
        }
        __syncthreads();
        {
            const int b = t & 31, kk0 = t >> 5;
            #pragma unroll
            for (int kk = kk0; kk < 32; kk += 8)
                g_featT2[(k0 + kk) * 512 + c * 32 + b] = tile[b][kk];
        }
    } else if (bid < PB_SCAN) {
        const int m = bid - PB_TR;
        if (t < 32) {
            const float lx = locs[m * 2 + 0];
            const float ly = locs[m * 2 + 1];
            int cnt = 0;
            for (int base = 0; base < KTOT; base += 32) {   // 576 = 18*32
                int k = base + t;
                int i = k / NQ, j = k - i * NQ;
                float x0 = lx - qn[j];
                float x1 = ly - qn[i];
                float r2 = x0 * x0 + x1 * x1;
                float da = DECAYF * r2 * r2;
                bool act = (da < 1.0f);
                unsigned bal = __ballot_sync(0xffffffffu, act);
                if (act) {
                    int pos = cnt + __popc(bal & ((1u << t) - 1u));
                    float bw = E_F * __expf(-1.0f / (1.0f - da)) * (qw[i] * qw[j]);
                    g_pts[m * PSTRIDE + pos] = make_float4(x0, x1, bw, __int_as_float(k));
                }
                cnt += __popc(bal);
            }
            if (t == 0) g_cnt[m] = cnt;
        }
    } else if (bid < PB_W) {
        const int w = bid - PB_SCAN;
        const int pair = t;
        float v;
        if (w < 16)      v = W1[pair * 16 + w];
        else if (w < 80) { int r = w - 16, g = r >> 3, h = r & 7;
                           v = W2[pair * 64 + h * 8 + g]; }
        else             v = W3[pair * 8 + (w - 80)];
        g_Wt[w * 256 + pair] = v;
    } else if (bid < PB_Z) {
        int idx = (bid - PB_W) * 256 + t;                  // 18432 float4 slots
        ((float4*)out)[idx] = make_float4(0.f, 0.f, 0.f, 0.f);
    }
}

__device__ __forceinline__ void cp8(uint32_t dst_smem, const void* src) {
    asm volatile("cp.async.ca.shared.global [%0], [%1], 8;\n"
                 :: "r"(dst_smem), "l"(src) : "memory");
}
#define CP_COMMIT() asm volatile("cp.async.commit_group;\n" ::: "memory")
#define CP_WAIT4()  asm volatile("cp.async.wait_group 4;\n" ::: "memory")

// ---------------------------------------------------------------------------
// Main: TWO points per iteration per thread — two independent MLP chains so
// the scheduler overlaps MUFU (sin) of one point with FMA of the other.
// 8 panel buffers; one commit group per point; barriers per 2 points.
// ---------------------------------------------------------------------------
__global__ void __launch_bounds__(256, 2)
qc_main(float* __restrict__ out) {
    const int t    = threadIdx.x;
    const int lane = t & 31;
    const int o    = t >> 4;
    const int bh   = t & 15;

    __shared__ __align__(16) float  s_f[8][BATCH * CI];   // 8x 2KB feature panels
    __shared__ __align__(16) float4 s_pts[MAXC];
    __shared__ float s_wb[HID * 256];   // w1b in smem (register relief)
    __shared__ float s_w3[HID * 256];   // w3 in smem
    __shared__ int s_pm[MAXC];
    __shared__ int s_off[MTOT + 1];

    // Weights: w1a + w2 in registers (72), w1b + w3 in smem
    float w1a[HID], w2t[HID][HID];
    {
        const float* W = g_Wt + t;
        #pragma unroll
        for (int h = 0; h < HID; h++) {
            w1a[h] = W[h * 256];
            s_wb[h * 256 + t] = W[(8 + h) * 256];
        }
        #pragma unroll
        for (int g = 0; g < HID; g++)
            #pragma unroll
            for (int h = 0; h < HID; h++) w2t[g][h] = W[(16 + g * 8 + h) * 256];
        #pragma unroll
        for (int g = 0; g < HID; g++) s_w3[g * 256 + t] = W[(80 + g) * 256];
    }

    // Warp 0: exclusive prefix over the 144 active counts
    if (t < 32) {
        int base = t * 5;
        int c0 = (base + 0 < MTOT) ? g_cnt[base + 0] : 0;
        int c1 = (base + 1 < MTOT) ? g_cnt[base + 1] : 0;
        int c2 = (base + 2 < MTOT) ? g_cnt[base + 2] : 0;
        int c3 = (base + 3 < MTOT) ? g_cnt[base + 3] : 0;
        int c4 = (base + 4 < MTOT) ? g_cnt[base + 4] : 0;
        int l0 = c0, l1 = l0 + c1, l2 = l1 + c2, l3 = l2 + c3, l4 = l3 + c4;
        int x = l4;
        #pragma unroll
        for (int d = 1; d < 32; d <<= 1) {
            int y = __shfl_up_sync(0xffffffffu, x, d);
            if (lane >= d) x += y;
        }
        int excl = x - l4;
        if (base + 0 <= MTOT) s_off[base + 0] = excl;
        if (base + 1 <= MTOT) s_off[base + 1] = excl + l0;
        if (base + 2 <= MTOT) s_off[base + 2] = excl + l1;
        if (base + 3 <= MTOT) s_off[base + 3] = excl + l2;
        if (base + 4 <= MTOT) s_off[base + 4] = excl + l3;
    }
    __syncthreads();

    const int T = s_off[MTOT];
    const int chunk = (T + NB - 1) / NB;
    const int p0 = blockIdx.x * chunk;
    const int n  = min(p0 + chunk, T) - p0;
    if (n <= 0) return;

    if (t < n) {
        int p = p0 + t;
        int lo = 0, hi = MTOT;
        while (hi - lo > 1) { int mid = (lo + hi) >> 1; (s_off[mid] <= p) ? (lo = mid) : (hi = mid); }
        s_pm[t]  = lo;
        s_pts[t] = g_pts[lo * PSTRIDE + (p - s_off[lo])];
    }
    __syncthreads();

    const uint32_t sfb   = (uint32_t)__cvta_generic_to_shared(&s_f[0][0]);
    const uint32_t myoff = (uint32_t)(t * 8);
    const float* swb = s_wb + t;
    const float* sw3 = s_w3 + t;

    // Prologue: one commit group per point for points 0..5 (empty kept)
    #pragma unroll
    for (int j = 0; j < 6; j++) {
        if (j < n)
            cp8(sfb + (uint32_t)(j & 7) * 2048 + myoff,
                g_featT2 + (size_t)__float_as_int(s_pts[j].w) * 512 + t * 2);
        CP_COMMIT();
    }

    int cm = s_pm[0];
    float a0 = 0.f, a1 = 0.f;
    const int nj = (n + 1) >> 1;

    for (int j = 0; j < nj; j++) {
        const int p = 2 * j;
        const bool hasB = (p + 1 < n);

        // Prefetch points p+6, p+7 (buffers (p+6)&7, (p+7)&7 — last read as
        // panels p-2, p-1 in iteration j-1, separated by its trailing sync)
        #pragma unroll
        for (int u = 0; u < 2; u++) {
            if (p + 6 + u < n)
                cp8(sfb + (uint32_t)((p + 6 + u) & 7) * 2048 + myoff,
                    g_featT2 + (size_t)__float_as_int(s_pts[p + 6 + u].w) * 512 + t * 2);
            CP_COMMIT();
        }

        // --- Two independent MLP chains (A = point p, B = point p+1) ---
        const float4 ptA = s_pts[p];
        const float4 ptB = hasB ? s_pts[p + 1] : ptA;
        float h1A[HID], h1B[HID];
        #pragma unroll
        for (int h = 0; h < HID; h++) {
            const float wb = swb[h * 256];
            h1A[h] = __sinf(fmaf(ptA.x, w1a[h], ptA.y * wb));
            h1B[h] = __sinf(fmaf(ptB.x, w1a[h], ptB.y * wb));
        }
        float valA = 0.f, valB = 0.f;
        #pragma unroll
        for (int g = 0; g < HID; g++) {
            float accA = 0.f, accB = 0.f;
            #pragma unroll
            for (int h = 0; h < HID; h++) {
                accA = fmaf(h1A[h], w2t[g][h], accA);
                accB = fmaf(h1B[h], w2t[g][h], accB);
            }
            const float w3v = sw3[g * 256];
            valA = fmaf(__sinf(accA), w3v, valA);
            valB = fmaf(__sinf(accB), w3v, valB);
        }
        const float vA = valA * ptA.z;
        const float vB = valB * ptB.z;

        // Panels p, p+1 complete: committed groups = p+8; <=4 pending after
        // wait => groups <= p+3 done, covering p and p+1.
        CP_WAIT4();
        __syncthreads();

        // --- Contraction for point p ---
        {
            const int m = s_pm[p];
            if (m != cm) {
                atomicAdd(&out[(2 * bh)     * (CO * MTOT) + o * MTOT + cm], a0);
                atomicAdd(&out[(2 * bh + 1) * (CO * MTOT) + o * MTOT + cm], a1);
                a0 = 0.f; a1 = 0.f; cm = m;
            }
            const float* fb = &s_f[p & 7][2 * bh];
            #pragma unroll
            for (int cc = 0; cc < CI; cc++) {
                float vv = __shfl_sync(0xffffffffu, vA, (lane & 16) + cc);
                float2 f = *(const float2*)(fb + cc * 32);
                a0 = fmaf(vv, f.x, a0);
                a1 = fmaf(vv, f.y, a1);
            }
        }
        // --- Contraction for point p+1 ---
        if (hasB) {
            const int m = s_pm[p + 1];
            if (m != cm) {
                atomicAdd(&out[(2 * bh)     * (CO * MTOT) + o * MTOT + cm], a0);
                atomicAdd(&out[(2 * bh + 1) * (CO * MTOT) + o * MTOT + cm], a1);
                a0 = 0.f; a1 = 0.f; cm = m;
            }
            const float* fb = &s_f[(p + 1) & 7][2 * bh];
            #pragma unroll
            for (int cc = 0; cc < CI; cc++) {
                float vv = __shfl_sync(0xffffffffu, vB, (lane & 16) + cc);
                float2 f = *(const float2*)(fb + cc * 32);
                a0 = fmaf(vv, f.x, a0);
                a1 = fmaf(vv, f.y, a1);
            }
        }
        __syncthreads();   // panel reads done before next iteration's clobber
    }

    atomicAdd(&out[(2 * bh)     * (CO * MTOT) + o * MTOT + cm], a0);
    atomicAdd(&out[(2 * bh + 1) * (CO * MTOT) + o * MTOT + cm], a1);
}

// ---------------------------------------------------------------------------
extern "C" void kernel_launch(void* const* d_in, const int* in_sizes, int n_in,
                              void* d_out, int out_size) {
    const float* feats = (const float*)d_in[0];  // (32, 16, 576)
    const float* locs  = (const float*)d_in[1];  // (144, 2)
    const float* qn    = (const float*)d_in[2];  // (24,)
    const float* qw    = (const float*)d_in[3];  // (24,)
    const float* W1    = (const float*)d_in[4];  // (16,16,2,8)
    const float* W2    = (const float*)d_in[5];  // (16,16,8,8)
    const float* W3    = (const float*)d_in[6];  // (16,16,8,1)
    float* out = (float*)d_out;                  // (32, 16, 144)

    qc_prep<<<PB_Z, 256>>>(feats, W1, W2, W3, locs, qn, qw, out);
    qc_main<<<NB, 256>>>(out);
}